// round 2
// baseline (speedup 1.0000x reference)
#include <cuda_runtime.h>

#define NUSERS 100000
#define NITEMS 50000
#define NNODES 150000
#define NEDGES 1200000
#define NV4    (NNODES * 16)   // float4 slots per embedding buffer (64 floats/node)

// Scratch: ping-pong embedding buffers + accumulator. 3 x 38.4 MB. (Static
// __device__ globals — no allocation, per harness rules.)
__device__ __align__(16) float4 g_a[NV4];
__device__ __align__(16) float4 g_b[NV4];
__device__ __align__(16) float4 g_acc[NV4];

// Vector global reduction (REDG.128): no return value, 4 floats per op.
__device__ __forceinline__ void red_add_f4(float4* p, float4 v) {
    asm volatile("red.global.add.v4.f32 [%0], {%1, %2, %3, %4};"
                 :: "l"(__cvta_generic_to_global(p)),
                    "f"(v.x), "f"(v.y), "f"(v.z), "f"(v.w)
                 : "memory");
}

// emb0 = concat(user_emb, item_emb); acc = emb0; b = 0.2*emb0 (prefill layer-0 dst)
__global__ __launch_bounds__(256) void k_init(const float* __restrict__ ue,
                                              const float* __restrict__ ie) {
    int i = blockIdx.x * 256 + threadIdx.x;
    if (i >= NV4) return;
    float4 v;
    if (i < NUSERS * 16) v = ((const float4*)ue)[i];
    else                 v = ((const float4*)ie)[i - NUSERS * 16];
    g_a[i]   = v;
    g_acc[i] = v;
    g_b[i]   = make_float4(0.2f * v.x, 0.2f * v.y, 0.2f * v.z, 0.2f * v.w);
}

// dst += 0.8 * val * src[col]   (dst prefilled with 0.2*src => dst ends as new emb)
// flip==0: src=g_a, dst=g_b ; flip==1: src=g_b, dst=g_a
__global__ __launch_bounds__(256) void k_scatter(const int* __restrict__ er,
                                                 const int* __restrict__ ec,
                                                 const float* __restrict__ ev,
                                                 int flip) {
    int t = blockIdx.x * 256 + threadIdx.x;
    int e = t >> 4;                 // 16 lanes per edge, one float4 per lane
    if (e >= NEDGES) return;
    int sub = t & 15;
    const float4* __restrict__ src = flip ? g_b : g_a;
    float4*       __restrict__ dst = flip ? g_a : g_b;
    int   row = er[e];
    int   col = ec[e];
    float v   = ev[e] * 0.8f;
    float4 x = src[col * 16 + sub];
    red_add_f4(&dst[row * 16 + sub],
               make_float4(x.x * v, x.y * v, x.z * v, x.w * v));
}

// acc += emb_new; optionally prefill the other buffer with 0.2*emb_new.
// flip==0: emb_new=g_b, prefill g_a ; flip==1: emb_new=g_a, prefill g_b
__global__ __launch_bounds__(256) void k_fix(int flip, int do_prefill) {
    int i = blockIdx.x * 256 + threadIdx.x;
    if (i >= NV4) return;
    const float4* __restrict__ nw = flip ? g_a : g_b;
    float4*       __restrict__ pf = flip ? g_b : g_a;
    float4 e = nw[i];
    float4 a = g_acc[i];
    g_acc[i] = make_float4(a.x + e.x, a.y + e.y, a.z + e.z, a.w + e.w);
    if (do_prefill)
        pf[i] = make_float4(0.2f * e.x, 0.2f * e.y, 0.2f * e.z, 0.2f * e.w);
}

// gamma[b] = dot(acc[u], acc[NUSERS+i]) / 16   (1/4 layer-mean on each side)
__global__ __launch_bounds__(256) void k_gamma(const int* __restrict__ users,
                                               const int* __restrict__ items,
                                               float* __restrict__ out) {
    int w    = (blockIdx.x * 256 + threadIdx.x) >> 5;  // warp per output
    int lane = threadIdx.x & 31;
    if (w >= 4096) return;
    int u  = users[w];
    int it = items[w];
    const float2* __restrict__ U = (const float2*)&g_acc[(size_t)u * 16];
    const float2* __restrict__ V = (const float2*)&g_acc[(size_t)(NUSERS + it) * 16];
    float2 a = U[lane];
    float2 b = V[lane];
    float s = a.x * b.x + a.y * b.y;
    #pragma unroll
    for (int o = 16; o; o >>= 1) s += __shfl_xor_sync(0xffffffffu, s, o);
    if (lane == 0) out[w] = s * (1.0f / 16.0f);
}

extern "C" void kernel_launch(void* const* d_in, const int* in_sizes, int n_in,
                              void* d_out, int out_size) {
    const int*   users = (const int*)  d_in[0];
    const int*   items = (const int*)  d_in[1];
    const int*   er    = (const int*)  d_in[2];
    const int*   ec    = (const int*)  d_in[3];
    const float* ev    = (const float*)d_in[4];
    const float* ue    = (const float*)d_in[5];
    const float* ie    = (const float*)d_in[6];
    float* out = (float*)d_out;

    const int STREAM_BLOCKS  = (NV4 + 255) / 256;            // 9375
    const int SCATTER_BLOCKS = (NEDGES * 16 + 255) / 256;    // 75000

    k_init<<<STREAM_BLOCKS, 256>>>(ue, ie);

    // Layer 1: src=g_a, dst=g_b
    k_scatter<<<SCATTER_BLOCKS, 256>>>(er, ec, ev, 0);
    k_fix<<<STREAM_BLOCKS, 256>>>(0, 1);
    // Layer 2: src=g_b, dst=g_a
    k_scatter<<<SCATTER_BLOCKS, 256>>>(er, ec, ev, 1);
    k_fix<<<STREAM_BLOCKS, 256>>>(1, 1);
    // Layer 3: src=g_a, dst=g_b
    k_scatter<<<SCATTER_BLOCKS, 256>>>(er, ec, ev, 0);
    k_fix<<<STREAM_BLOCKS, 256>>>(0, 0);

    k_gamma<<<4096 / 8, 256>>>(users, items, out);
}

// round 5
// speedup vs baseline: 1.9864x; 1.9864x over previous
#include <cuda_runtime.h>

#define NUSERS 100000
#define NITEMS 50000
#define NNODES 150000
#define NEDGES 1200000
#define NV4    (NNODES * 16)        // float4 slots per embedding buffer
#define SCAN_B 1024
#define NBLK   ((NNODES + SCAN_B - 1) / SCAN_B)   // 147

// Layer embedding buffers e0..e3 (4 x 38.4 MB) + CSR scratch. Static globals only.
__device__ __align__(16) float4 g_e0[NV4];
__device__ __align__(16) float4 g_e1[NV4];
__device__ __align__(16) float4 g_e2[NV4];
__device__ __align__(16) float4 g_e3[NV4];
__device__ int  g_cnt[NNODES];
__device__ int  g_pos[NNODES];
__device__ int  g_rowptr[NNODES + 1];
__device__ int  g_bsum[NBLK];
__device__ __align__(8) int2 g_edges[NEDGES];   // {col, __float_as_int(0.8*val)}

// Device-side layer-buffer selection (NEVER reference device symbols from host!)
__device__ __forceinline__ float4* layer_buf(int k) {
    switch (k) {
        case 0:  return g_e0;
        case 1:  return g_e1;
        case 2:  return g_e2;
        default: return g_e3;
    }
}

// e0 = concat(user_emb, item_emb); also zero the CSR counters.
__global__ __launch_bounds__(256) void k_init(const float* __restrict__ ue,
                                              const float* __restrict__ ie) {
    int i = blockIdx.x * 256 + threadIdx.x;
    if (i < NNODES) { g_cnt[i] = 0; g_pos[i] = 0; }
    if (i >= NV4) return;
    float4 v;
    if (i < NUSERS * 16) v = ((const float4*)ue)[i];
    else                 v = ((const float4*)ie)[i - NUSERS * 16];
    g_e0[i] = v;
}

__global__ __launch_bounds__(256) void k_hist(const int* __restrict__ er) {
    int e = blockIdx.x * 256 + threadIdx.x;
    if (e < NEDGES) atomicAdd(&g_cnt[er[e]], 1);
}

// Exclusive scan of g_cnt -> g_rowptr, 3-kernel hierarchical (Hillis-Steele per block).
__global__ __launch_bounds__(SCAN_B) void k_scan1() {
    __shared__ int sh[SCAN_B];
    int idx = blockIdx.x * SCAN_B + threadIdx.x;
    int v = (idx < NNODES) ? g_cnt[idx] : 0;
    sh[threadIdx.x] = v;
    __syncthreads();
    #pragma unroll
    for (int o = 1; o < SCAN_B; o <<= 1) {
        int t = (threadIdx.x >= o) ? sh[threadIdx.x - o] : 0;
        __syncthreads();
        sh[threadIdx.x] += t;
        __syncthreads();
    }
    int incl = sh[threadIdx.x];
    if (idx < NNODES) g_rowptr[idx] = incl - v;        // exclusive
    if (threadIdx.x == SCAN_B - 1) g_bsum[blockIdx.x] = incl;
}

__global__ void k_scan2() {
    if (threadIdx.x == 0) {
        int run = 0;
        for (int b = 0; b < NBLK; b++) { int t = g_bsum[b]; g_bsum[b] = run; run += t; }
    }
}

__global__ __launch_bounds__(SCAN_B) void k_scan3() {
    int idx = blockIdx.x * SCAN_B + threadIdx.x;
    if (idx < NNODES) g_rowptr[idx] += g_bsum[blockIdx.x];
    if (idx == 0) g_rowptr[NNODES] = NEDGES;
}

// Place each edge into its row segment (order within row is arbitrary).
__global__ __launch_bounds__(256) void k_reorder(const int* __restrict__ er,
                                                 const int* __restrict__ ec,
                                                 const float* __restrict__ ev) {
    int e = blockIdx.x * 256 + threadIdx.x;
    if (e >= NEDGES) return;
    int row = er[e];
    int pos = g_rowptr[row] + atomicAdd(&g_pos[row], 1);
    g_edges[pos] = make_int2(ec[e], __float_as_int(ev[e] * 0.8f));
}

// dst[row] = 0.2*src[row] + sum_e (0.8*val_e) * src[col_e]   -- 16 lanes per row.
__global__ __launch_bounds__(256) void k_prop(int layer) {
    const float4* __restrict__ src = layer_buf(layer);
    float4*       __restrict__ dst = layer_buf(layer + 1);
    int t   = blockIdx.x * 256 + threadIdx.x;
    int row = t >> 4;
    if (row >= NNODES) return;
    int sub = t & 15;
    int beg = g_rowptr[row];
    int end = g_rowptr[row + 1];

    float4 own = src[row * 16 + sub];
    float4 s = make_float4(0.2f * own.x, 0.2f * own.y, 0.2f * own.z, 0.2f * own.w);

    int e = beg;
    for (; e + 1 < end; e += 2) {            // 2-way unroll for MLP
        int2 p0 = g_edges[e];
        int2 p1 = g_edges[e + 1];
        float4 x0 = src[p0.x * 16 + sub];
        float4 x1 = src[p1.x * 16 + sub];
        float v0 = __int_as_float(p0.y);
        float v1 = __int_as_float(p1.y);
        s.x += v0 * x0.x; s.y += v0 * x0.y; s.z += v0 * x0.z; s.w += v0 * x0.w;
        s.x += v1 * x1.x; s.y += v1 * x1.y; s.z += v1 * x1.z; s.w += v1 * x1.w;
    }
    if (e < end) {
        int2 p0 = g_edges[e];
        float4 x0 = src[p0.x * 16 + sub];
        float v0 = __int_as_float(p0.y);
        s.x += v0 * x0.x; s.y += v0 * x0.y; s.z += v0 * x0.z; s.w += v0 * x0.w;
    }
    dst[row * 16 + sub] = s;
}

// gamma[b] = dot(sum_k e_k[u], sum_k e_k[NUSERS+i]) / 16
__global__ __launch_bounds__(256) void k_gamma(const int* __restrict__ users,
                                               const int* __restrict__ items,
                                               float* __restrict__ out) {
    int w    = (blockIdx.x * 256 + threadIdx.x) >> 5;   // warp per output pair
    int lane = threadIdx.x & 31;
    if (w >= 4096) return;
    size_t u = (size_t)users[w] * 16;
    size_t v = (size_t)(NUSERS + items[w]) * 16;

    float2 a0 = ((const float2*)&g_e0[u])[lane];
    float2 a1 = ((const float2*)&g_e1[u])[lane];
    float2 a2 = ((const float2*)&g_e2[u])[lane];
    float2 a3 = ((const float2*)&g_e3[u])[lane];
    float2 b0 = ((const float2*)&g_e0[v])[lane];
    float2 b1 = ((const float2*)&g_e1[v])[lane];
    float2 b2 = ((const float2*)&g_e2[v])[lane];
    float2 b3 = ((const float2*)&g_e3[v])[lane];

    float ax = a0.x + a1.x + a2.x + a3.x;
    float ay = a0.y + a1.y + a2.y + a3.y;
    float bx = b0.x + b1.x + b2.x + b3.x;
    float by = b0.y + b1.y + b2.y + b3.y;

    float s = ax * bx + ay * by;
    #pragma unroll
    for (int o = 16; o; o >>= 1) s += __shfl_xor_sync(0xffffffffu, s, o);
    if (lane == 0) out[w] = s * (1.0f / 16.0f);
}

extern "C" void kernel_launch(void* const* d_in, const int* in_sizes, int n_in,
                              void* d_out, int out_size) {
    const int*   users = (const int*)  d_in[0];
    const int*   items = (const int*)  d_in[1];
    const int*   er    = (const int*)  d_in[2];
    const int*   ec    = (const int*)  d_in[3];
    const float* ev    = (const float*)d_in[4];
    const float* ue    = (const float*)d_in[5];
    const float* ie    = (const float*)d_in[6];
    float* out = (float*)d_out;

    const int STREAM_BLOCKS = (NV4 + 255) / 256;        // 9375
    const int EDGE_BLOCKS   = (NEDGES + 255) / 256;     // 4688

    k_init<<<STREAM_BLOCKS, 256>>>(ue, ie);

    // Build CSR (amortized over 3 propagation layers)
    k_hist<<<EDGE_BLOCKS, 256>>>(er);
    k_scan1<<<NBLK, SCAN_B>>>();
    k_scan2<<<1, 32>>>();
    k_scan3<<<NBLK, SCAN_B>>>();
    k_reorder<<<EDGE_BLOCKS, 256>>>(er, ec, ev);

    // 3 propagation layers, no atomics (buffers selected in device code)
    k_prop<<<STREAM_BLOCKS, 256>>>(0);
    k_prop<<<STREAM_BLOCKS, 256>>>(1);
    k_prop<<<STREAM_BLOCKS, 256>>>(2);

    k_gamma<<<4096 / 8, 256>>>(users, items, out);
}